// round 1
// baseline (speedup 1.0000x reference)
#include <cuda_runtime.h>
#include <cuda_bf16.h>
#include <math.h>

// ---------------------------------------------------------------------------
// Problem constants
// ---------------------------------------------------------------------------
#define BB    4
#define SS    1020
#define DDIM  1024
#define HH    16
#define DH    64
#define LL    4
#define TPB_  17
#define FF    4096
#define NTOK  (BB * SS)          // 4080
#define NOBS  (BB * 960)         // 3840 rows for obs head
#define NACT  (BB * 60)          // 240 rows for ends head
#define VOBS_ 4096
#define VACT_ 16

// ---------------------------------------------------------------------------
// Static device scratch (no runtime allocation allowed)
// ---------------------------------------------------------------------------
__device__ float g_x   [NTOK * DDIM];
__device__ float g_h   [NTOK * DDIM];
__device__ float g_q   [NTOK * DDIM];
__device__ float g_k   [NTOK * DDIM];
__device__ float g_v   [NTOK * DDIM];
__device__ float g_o   [NTOK * DDIM];
__device__ float g_mid [NTOK * FF];
__device__ float g_t1  [NOBS * DDIM];
__device__ float g_t2  [NACT * DDIM];
__device__ int   g_obs_rows[NOBS];
__device__ int   g_act_rows[NACT];

// ---------------------------------------------------------------------------
// Embedding: x[b,s,:] = (is_obs ? emb_obs[tok] : emb_act[tok]) + pos_emb[s]
// ---------------------------------------------------------------------------
__global__ void embed_kernel(const int* __restrict__ tokens,
                             const float* __restrict__ pos_emb,
                             const float* __restrict__ emb_obs,
                             const float* __restrict__ emb_act,
                             float* __restrict__ x)
{
    int row = blockIdx.x;                 // 0..NTOK-1
    int s   = row % SS;
    int tok = tokens[row];
    bool is_obs = (s % TPB_) < (TPB_ - 1);
    const float* e = is_obs ? (emb_obs + (size_t)min(tok, VOBS_ - 1) * DDIM)
                            : (emb_act + (size_t)min(tok, VACT_ - 1) * DDIM);
    const float* pe = pos_emb + (size_t)s * DDIM;
    float* xo = x + (size_t)row * DDIM;
    for (int d = threadIdx.x; d < DDIM; d += blockDim.x)
        xo[d] = e[d] + pe[d];
}

// ---------------------------------------------------------------------------
// Block reduction (256 threads)
// ---------------------------------------------------------------------------
__device__ __forceinline__ float block_sum256(float v)
{
    __shared__ float sh[8];
    int lane = threadIdx.x & 31, w = threadIdx.x >> 5;
    #pragma unroll
    for (int o = 16; o > 0; o >>= 1) v += __shfl_xor_sync(0xffffffffu, v, o);
    if (lane == 0) sh[w] = v;
    __syncthreads();
    if (w == 0) {
        float t = (lane < 8) ? sh[lane] : 0.f;
        #pragma unroll
        for (int o = 4; o > 0; o >>= 1) t += __shfl_xor_sync(0xffffffffu, t, o);
        if (lane == 0) sh[0] = t;
    }
    __syncthreads();
    float r = sh[0];
    __syncthreads();
    return r;
}

// ---------------------------------------------------------------------------
// LayerNorm: one block (256 threads) per row, 4 elems/thread
// ---------------------------------------------------------------------------
__global__ void ln_kernel(const float* __restrict__ x,
                          const float* __restrict__ g,
                          const float* __restrict__ b,
                          float* __restrict__ out)
{
    int row = blockIdx.x;
    const float* xr = x + (size_t)row * DDIM;
    float* orow = out + (size_t)row * DDIM;
    int t = threadIdx.x;
    float v[4];
    float s = 0.f;
    #pragma unroll
    for (int i = 0; i < 4; ++i) { v[i] = xr[t + 256 * i]; s += v[i]; }
    float mean = block_sum256(s) * (1.f / (float)DDIM);
    float q = 0.f;
    #pragma unroll
    for (int i = 0; i < 4; ++i) { float d = v[i] - mean; q += d * d; }
    float var  = block_sum256(q) * (1.f / (float)DDIM);
    float rstd = rsqrtf(var + 1e-3f);
    #pragma unroll
    for (int i = 0; i < 4; ++i) {
        int idx = t + 256 * i;
        orow[idx] = (v[i] - mean) * rstd * g[idx] + b[idx];
    }
}

// ---------------------------------------------------------------------------
// Generic fp32 GEMM: C[M,N] = act(A[M,K] @ W[K,N] + bias) (+ resid)
// BM=128, BN=128, BK=8, 256 threads, 8x8 per-thread tile.
// rowmap (optional): A-row index for output row m (gather).
// ACT: 0 = none, 1 = exact GELU, 2 = ReLU
// ---------------------------------------------------------------------------
template<int ACT>
__global__ __launch_bounds__(256)
void gemm_kernel(const float* __restrict__ A, const float* __restrict__ W,
                 const float* __restrict__ bias, float* __restrict__ C,
                 const float* __restrict__ resid, const int* __restrict__ rowmap,
                 int M, int N, int K)
{
    __shared__ float As[8][128];
    __shared__ float Ws[8][128];

    int tid = threadIdx.x;
    int m0 = blockIdx.y * 128;
    int n0 = blockIdx.x * 128;
    int tx = tid & 15;   // n sub-tile
    int ty = tid >> 4;   // m sub-tile

    float acc[8][8];
    #pragma unroll
    for (int i = 0; i < 8; ++i)
        #pragma unroll
        for (int j = 0; j < 8; ++j) acc[i][j] = 0.f;

    // A tile loader: each thread loads one float4
    int arow = tid >> 1;               // 0..127
    int acol = (tid & 1) * 4;          // 0 or 4
    int am   = m0 + arow;
    int amap = -1;
    if (am < M) amap = rowmap ? rowmap[am] : am;
    const float* Aptr = (amap >= 0) ? (A + (size_t)amap * K + acol) : A;

    // W tile loader
    int wrow = tid >> 5;               // 0..7
    int wcol = (tid & 31) * 4;         // 0..124
    const float* Wptr = W + (size_t)wrow * N + n0 + wcol;

    for (int k0 = 0; k0 < K; k0 += 8) {
        float4 av = (amap >= 0) ? *(const float4*)Aptr : make_float4(0.f, 0.f, 0.f, 0.f);
        float4 wv = *(const float4*)Wptr;
        __syncthreads();
        As[acol + 0][arow] = av.x;
        As[acol + 1][arow] = av.y;
        As[acol + 2][arow] = av.z;
        As[acol + 3][arow] = av.w;
        *(float4*)&Ws[wrow][wcol] = wv;
        __syncthreads();
        #pragma unroll
        for (int kk = 0; kk < 8; ++kk) {
            float a[8], w[8];
            #pragma unroll
            for (int i = 0; i < 8; ++i) a[i] = As[kk][ty + 16 * i];
            #pragma unroll
            for (int j = 0; j < 8; ++j) w[j] = Ws[kk][tx + 16 * j];
            #pragma unroll
            for (int i = 0; i < 8; ++i)
                #pragma unroll
                for (int j = 0; j < 8; ++j)
                    acc[i][j] = fmaf(a[i], w[j], acc[i][j]);
        }
        Aptr += 8;
        Wptr += (size_t)8 * N;
    }

    #pragma unroll
    for (int i = 0; i < 8; ++i) {
        int m = m0 + ty + 16 * i;
        if (m >= M) continue;
        #pragma unroll
        for (int j = 0; j < 8; ++j) {
            int n = n0 + tx + 16 * j;
            float vv = acc[i][j] + bias[n];
            if (ACT == 1) vv = 0.5f * vv * (1.0f + erff(vv * 0.70710678118654752f));
            if (ACT == 2) vv = fmaxf(vv, 0.f);
            if (resid) vv += resid[(size_t)m * N + n];
            C[(size_t)m * N + n] = vv;
        }
    }
}

// ---------------------------------------------------------------------------
// Fused causal attention (flash-style online softmax).
// grid: (num q-tiles of 64, B*H), block: 64 threads (1 thread = 1 query row)
// q/k/v layout: [B*S, D] with head h at column h*DH.
// ---------------------------------------------------------------------------
__global__ void attn_kernel(const float* __restrict__ q,
                            const float* __restrict__ k,
                            const float* __restrict__ v,
                            float* __restrict__ o)
{
    int bh = blockIdx.y;            // 0..B*H-1
    int b = bh >> 4, h = bh & 15;
    int qt = blockIdx.x;
    int tid = threadIdx.x;          // 0..63
    int i = qt * 64 + tid;
    bool valid = i < SS;
    int irow = valid ? i : SS - 1;
    size_t base = (size_t)b * SS * DDIM + (size_t)h * DH;

    float qreg[64];
    {
        const float4* q4 = (const float4*)(q + base + (size_t)irow * DDIM);
        #pragma unroll
        for (int d4 = 0; d4 < 16; ++d4) {
            float4 t = q4[d4];
            qreg[4 * d4 + 0] = t.x; qreg[4 * d4 + 1] = t.y;
            qreg[4 * d4 + 2] = t.z; qreg[4 * d4 + 3] = t.w;
        }
    }

    __shared__ float4 Ksh[64][16];
    __shared__ float4 Vsh[64][16];

    float oacc[64];
    #pragma unroll
    for (int d = 0; d < 64; ++d) oacc[d] = 0.f;
    float m = -1e30f, l = 0.f;
    const float scale = 0.125f;     // 1/sqrt(64)

    for (int kt = 0; kt <= qt; ++kt) {
        int j0 = kt * 64;
        int nk = min(64, SS - j0);
        __syncthreads();
        #pragma unroll
        for (int it = 0; it < 16; ++it) {
            int idx = it * 64 + tid;
            int j = idx >> 4, d4 = idx & 15;
            if (j < nk) {
                Ksh[j][d4] = *(const float4*)(k + base + (size_t)(j0 + j) * DDIM + 4 * d4);
                Vsh[j][d4] = *(const float4*)(v + base + (size_t)(j0 + j) * DDIM + 4 * d4);
            }
        }
        __syncthreads();
        if (valid) {
            const float* Ks = (const float*)Ksh;
            const float* Vs = (const float*)Vsh;
            int jend = min(nk, i - j0 + 1);
            for (int j = 0; j < jend; ++j) {
                const float* kr = Ks + j * 64;
                float s = 0.f;
                #pragma unroll
                for (int d = 0; d < 64; ++d) s = fmaf(qreg[d], kr[d], s);
                s *= scale;
                const float* vr = Vs + j * 64;
                if (s > m) {
                    float c = __expf(m - s);
                    l = l * c + 1.f;
                    #pragma unroll
                    for (int d = 0; d < 64; ++d) oacc[d] = fmaf(oacc[d], c, vr[d]);
                    m = s;
                } else {
                    float p = __expf(s - m);
                    l += p;
                    #pragma unroll
                    for (int d = 0; d < 64; ++d) oacc[d] = fmaf(p, vr[d], oacc[d]);
                }
            }
        }
    }

    if (valid) {
        float inv = 1.f / l;
        float* orow = o + base + (size_t)irow * DDIM;
        #pragma unroll
        for (int d = 0; d < 64; ++d) orow[d] = oacc[d] * inv;
    }
}

// ---------------------------------------------------------------------------
// Build gather indices for the two heads
// obs rows: p % 17 != 15 (16/block of 17); act rows: p % 17 == 16
// ---------------------------------------------------------------------------
__global__ void build_idx_kernel()
{
    int t = blockIdx.x * blockDim.x + threadIdx.x;
    if (t < NOBS) {
        int b = t / 960, j = t % 960;
        int blk = j / 16, r = j % 16;
        int p = blk * TPB_ + (r < 15 ? r : 16);
        g_obs_rows[t] = b * SS + p;
    }
    if (t < NACT) {
        int b = t / 60, blk = t % 60;
        g_act_rows[t] = b * SS + blk * TPB_ + (TPB_ - 1);
    }
}

// ---------------------------------------------------------------------------
// Tiny N=2 head: logits_ends = t2 @ he2 + be2
// ---------------------------------------------------------------------------
__global__ void head_ends_kernel(const float* __restrict__ t2,
                                 const float* __restrict__ w,
                                 const float* __restrict__ bias,
                                 float* __restrict__ out)
{
    int r = blockIdx.x;
    int tid = threadIdx.x;  // 128
    const float* a = t2 + (size_t)r * DDIM;
    float s0 = 0.f, s1 = 0.f;
    for (int kk = tid; kk < DDIM; kk += 128) {
        float av = a[kk];
        s0 = fmaf(av, w[kk * 2 + 0], s0);
        s1 = fmaf(av, w[kk * 2 + 1], s1);
    }
    __shared__ float red[128];
    red[tid] = s0; __syncthreads();
    for (int st = 64; st > 0; st >>= 1) { if (tid < st) red[tid] += red[tid + st]; __syncthreads(); }
    if (tid == 0) out[r * 2 + 0] = red[0] + bias[0];
    __syncthreads();
    red[tid] = s1; __syncthreads();
    for (int st = 64; st > 0; st >>= 1) { if (tid < st) red[tid] += red[tid + st]; __syncthreads(); }
    if (tid == 0) out[r * 2 + 1] = red[0] + bias[1];
}

// ---------------------------------------------------------------------------
// Launch
// ---------------------------------------------------------------------------
extern "C" void kernel_launch(void* const* d_in, const int* in_sizes, int n_in,
                              void* d_out, int out_size)
{
    const int*   tokens  = (const int*)  d_in[0];
    const float* pos_emb = (const float*)d_in[1];
    const float* emb_obs = (const float*)d_in[2];
    const float* emb_act = (const float*)d_in[3];
    const float* ln1_g   = (const float*)d_in[4];
    const float* ln1_b   = (const float*)d_in[5];
    const float* wq      = (const float*)d_in[6];
    const float* bq      = (const float*)d_in[7];
    const float* wk      = (const float*)d_in[8];
    const float* bk      = (const float*)d_in[9];
    const float* wv      = (const float*)d_in[10];
    const float* bv      = (const float*)d_in[11];
    const float* wo      = (const float*)d_in[12];
    const float* bo      = (const float*)d_in[13];
    const float* ln2_g   = (const float*)d_in[14];
    const float* ln2_b   = (const float*)d_in[15];
    const float* w1      = (const float*)d_in[16];
    const float* b1      = (const float*)d_in[17];
    const float* w2      = (const float*)d_in[18];
    const float* b2      = (const float*)d_in[19];
    const float* lnf_g   = (const float*)d_in[20];
    const float* lnf_b   = (const float*)d_in[21];
    const float* ho1     = (const float*)d_in[22];
    const float* bo1     = (const float*)d_in[23];
    const float* ho2     = (const float*)d_in[24];
    const float* bo2     = (const float*)d_in[25];
    const float* he1     = (const float*)d_in[26];
    const float* be1     = (const float*)d_in[27];
    const float* he2     = (const float*)d_in[28];
    const float* be2     = (const float*)d_in[29];
    float* out = (float*)d_out;

    float *x, *h, *q, *k, *v, *o, *mid, *t1, *t2;
    int *obsr, *actr;
    cudaGetSymbolAddress((void**)&x,   g_x);
    cudaGetSymbolAddress((void**)&h,   g_h);
    cudaGetSymbolAddress((void**)&q,   g_q);
    cudaGetSymbolAddress((void**)&k,   g_k);
    cudaGetSymbolAddress((void**)&v,   g_v);
    cudaGetSymbolAddress((void**)&o,   g_o);
    cudaGetSymbolAddress((void**)&mid, g_mid);
    cudaGetSymbolAddress((void**)&t1,  g_t1);
    cudaGetSymbolAddress((void**)&t2,  g_t2);
    cudaGetSymbolAddress((void**)&obsr, g_obs_rows);
    cudaGetSymbolAddress((void**)&actr, g_act_rows);

    const int MB = (NTOK + 127) / 128;   // 32
    dim3 gD(DDIM / 128, MB);             // (8, 32)
    dim3 gF(FF / 128, MB);               // (32, 32)

    embed_kernel<<<NTOK, 256>>>(tokens, pos_emb, emb_obs, emb_act, x);

    for (int l = 0; l < LL; ++l) {
        size_t wofs = (size_t)l * DDIM * DDIM;
        ln_kernel<<<NTOK, 256>>>(x, ln1_g + l * DDIM, ln1_b + l * DDIM, h);
        gemm_kernel<0><<<gD, 256>>>(h, wq + wofs, bq + l * DDIM, q, nullptr, nullptr, NTOK, DDIM, DDIM);
        gemm_kernel<0><<<gD, 256>>>(h, wk + wofs, bk + l * DDIM, k, nullptr, nullptr, NTOK, DDIM, DDIM);
        gemm_kernel<0><<<gD, 256>>>(h, wv + wofs, bv + l * DDIM, v, nullptr, nullptr, NTOK, DDIM, DDIM);
        attn_kernel<<<dim3((SS + 63) / 64, BB * HH), 64>>>(q, k, v, o);
        gemm_kernel<0><<<gD, 256>>>(o, wo + wofs, bo + l * DDIM, x, x, nullptr, NTOK, DDIM, DDIM);
        ln_kernel<<<NTOK, 256>>>(x, ln2_g + l * DDIM, ln2_b + l * DDIM, h);
        gemm_kernel<1><<<gF, 256>>>(h, w1 + (size_t)l * DDIM * FF, b1 + (size_t)l * FF, mid,
                                    nullptr, nullptr, NTOK, FF, DDIM);
        gemm_kernel<0><<<gD, 256>>>(mid, w2 + (size_t)l * FF * DDIM, b2 + l * DDIM, x,
                                    x, nullptr, NTOK, DDIM, FF);
    }

    ln_kernel<<<NTOK, 256>>>(x, lnf_g, lnf_b, h);
    build_idx_kernel<<<(NOBS + 255) / 256, 256>>>();

    // obs head: gather -> relu(x@ho1+bo1) -> @ho2+bo2 -> out[0 : NOBS*4096)
    gemm_kernel<2><<<dim3(DDIM / 128, (NOBS + 127) / 128), 256>>>(
        h, ho1, bo1, t1, nullptr, obsr, NOBS, DDIM, DDIM);
    gemm_kernel<0><<<dim3(VOBS_ / 128, (NOBS + 127) / 128), 256>>>(
        t1, ho2, bo2, out, nullptr, nullptr, NOBS, VOBS_, DDIM);

    // ends head: gather -> relu(x@he1+be1) -> @he2+be2 -> out[NOBS*4096 : ...)
    gemm_kernel<2><<<dim3(DDIM / 128, (NACT + 127) / 128), 256>>>(
        h, he1, be1, t2, nullptr, actr, NACT, DDIM, DDIM);
    head_ends_kernel<<<NACT, 128>>>(t2, he2, be2, out + (size_t)NOBS * VOBS_);
}